// round 3
// baseline (speedup 1.0000x reference)
#include <cuda_runtime.h>
#include <cstdint>

#define N_PULSES 64
#define N_STATES 21

__global__ __launch_bounds__(256, 4)
void epg_kernel(const float* __restrict__ flip,
                const float* __restrict__ phases,
                const float* __restrict__ T1,
                const float* __restrict__ T2,
                const float* __restrict__ B0,
                const float* __restrict__ B1,
                const void*  __restrict__ trp,
                float* __restrict__ out,
                int B)
{
    // Per-pulse constants: (cb, sb, c2b, s2b) packed for one LDS.128, half-angle separate
    __shared__ float4 s_c[N_PULSES];
    __shared__ float  s_ha[N_PULSES];

    int tid = threadIdx.x;
    if (tid < N_PULSES) {
        float bph = phases[tid];
        float sb, cb;
        sincosf(bph, &sb, &cb);
        s_c[tid]  = make_float4(cb, sb, cb * cb - sb * sb, 2.0f * cb * sb);
        s_ha[tid] = 0.5f * flip[tid];
    }
    __syncthreads();

    int gwarp = (int)((blockIdx.x * blockDim.x + tid) >> 5);
    int lane  = tid & 31;
    if (gwarp >= B) return;
    int b = gwarp;

    // TR: defensive decode (int32 / float32 both yield 500)
    float TRf;
    {
        int iv = *(const int*)trp;
        if (iv > 0 && iv < 1000000) TRf = (float)iv;
        else                        TRf = *(const float*)trp;
    }

    float t1v = T1[b], t2v = T2[b], b0v = B0[b], b1v = B1[b];
    float E1 = expf(-TRf / t1v);
    float E2 = expf(-TRf / t2v);
    float one_mE1 = 1.0f - E1;

    float phi = 2.0f * 3.14159265358979f * b0v * TRf * 0.001f;
    float sphi, cphi;
    sincosf(phi, &sphi, &cphi);

    // Fused relaxation + off-resonance: Fp *= E2*e^{+i phi}, Fm *= E2*e^{-i phi}
    float cE = E2 * cphi;
    float sE = E2 * sphi;

    // State (per lane = per EPG order). Lanes >= N_STATES carry junk but stay in lockstep.
    float FpR = 0.f, FpI = 0.f, FmR = 0.f, FmI = 0.f;
    float Z = (lane == 0) ? 1.0f : 0.0f;

    size_t planeStride = (size_t)B * N_STATES;
    float* outp = out + (size_t)b * N_STATES + lane;
    size_t pulseStride = 5 * planeStride;
    bool doStore = (lane < N_STATES);
    bool isLane0 = (lane == 0);
    bool isLast  = (lane == N_STATES - 1);

    #pragma unroll 2
    for (int p = 0; p < N_PULSES; p++) {
        // Fused E2 relaxation + B0 rotation (one complex multiply each)
        float r;
        r   = FpR * cE - FpI * sE;
        FpI = FpR * sE + FpI * cE;
        FpR = r;
        r   = FmR * cE + FmI * sE;
        FmI = FmI * cE - FmR * sE;
        FmR = r;

        // Z relaxation + recovery (lane 0 only)
        Z *= E1;
        if (isLane0) Z += one_mE1;

        // RF pulse mixing — hardware sincos
        float sa, ca;
        __sincosf(s_ha[p] * b1v, &sa, &ca);
        float4 c = s_c[p];
        float cb = c.x, sb = c.y, c2b = c.z, s2b = c.w;
        float ca2 = ca * ca, sa2 = sa * sa, casa = ca * sa;
        float cZ = casa * Z;

        float FpnR = ca2 * FpR + sa2 * ( FmR * c2b + FmI * s2b) - cZ * sb;
        float FpnI = ca2 * FpI + sa2 * ( FmR * s2b - FmI * c2b) + cZ * cb;
        float FmnR = ca2 * FmR + sa2 * ( FpR * c2b - FpI * s2b) - cZ * sb;
        float FmnI = ca2 * FmI + sa2 * (-FpR * s2b - FpI * c2b) - cZ * cb;
        float Dim  = (FpI * cb - FpR * sb) - (FmR * sb + FmI * cb);
        float Zn   = casa * Dim + (ca2 - sa2) * Z;

        // Gradient shift: Fp states move up one order, Fm down one order
        float FpsR = __shfl_up_sync(0xffffffffu, FpnR, 1);
        float FpsI = __shfl_up_sync(0xffffffffu, FpnI, 1);
        float FmsR = __shfl_down_sync(0xffffffffu, FmnR, 1);
        float FmsI = __shfl_down_sync(0xffffffffu, FmnI, 1);
        if (isLane0) { FpsR = 0.f; FpsI = 0.f; }
        if (isLast)  { FmsR = 0.f; FmsI = 0.f; }
        FpR = FpsR; FpI = FpsI; FmR = FmsR; FmI = FmsI; Z = Zn;

        // Store outs[p, 0..4, b, lane]
        if (doStore) {
            outp[0]               = FpR;
            outp[planeStride]     = FpI;
            outp[2 * planeStride] = FmR;
            outp[3 * planeStride] = FmI;
            outp[4 * planeStride] = Zn;
        }
        outp += pulseStride;
    }
}

extern "C" void kernel_launch(void* const* d_in, const int* in_sizes, int n_in,
                              void* d_out, int out_size)
{
    const float* flip   = (const float*)d_in[0];
    const float* phases = (const float*)d_in[1];
    const float* T1     = (const float*)d_in[2];
    const float* T2     = (const float*)d_in[3];
    const float* B0     = (const float*)d_in[4];
    const float* B1     = (const float*)d_in[5];
    const void*  trp    = d_in[6];
    float* out = (float*)d_out;

    int B = in_sizes[2];               // batch from T1
    int threads = 256;
    int warpsPerBlock = threads / 32;
    int blocks = (B + warpsPerBlock - 1) / warpsPerBlock;

    epg_kernel<<<blocks, threads>>>(flip, phases, T1, T2, B0, B1, trp, out, B);
}

// round 4
// speedup vs baseline: 1.1313x; 1.1313x over previous
#include <cuda_runtime.h>
#include <cstdint>

#define N_PULSES 64
#define N_STATES 21

__global__ __launch_bounds__(256)
void epg_kernel(const float* __restrict__ flip,
                const float* __restrict__ phases,
                const float* __restrict__ T1,
                const float* __restrict__ T2,
                const float* __restrict__ B0,
                const float* __restrict__ B1,
                const void*  __restrict__ trp,
                float* __restrict__ out,
                int B)
{
    // Per-pulse constants: (cb, sb, c2b, s2b) packed for one LDS.128, half-angle separate
    __shared__ float4 s_c[N_PULSES];
    __shared__ float  s_ha[N_PULSES];

    int tid = threadIdx.x;
    if (tid < N_PULSES) {
        float bph = phases[tid];
        float sb, cb;
        sincosf(bph, &sb, &cb);
        s_c[tid]  = make_float4(cb, sb, cb * cb - sb * sb, 2.0f * cb * sb);
        s_ha[tid] = 0.5f * flip[tid];
    }
    __syncthreads();

    int gwarp = (int)((blockIdx.x * blockDim.x + tid) >> 5);
    int lane  = tid & 31;

    // Each warp simulates TWO independent batch elements (ILP over occupancy)
    int b0 = 2 * gwarp;
    int b1 = b0 + 1;
    if (b0 >= B) return;
    bool has1 = (b1 < B);
    int b1c = has1 ? b1 : b0;   // clamp loads; stores guarded

    // TR: defensive decode (int32 / float32 both yield 500)
    float TRf;
    {
        int iv = *(const int*)trp;
        if (iv > 0 && iv < 1000000) TRf = (float)iv;
        else                        TRf = *(const float*)trp;
    }

    // Per-element prologue
    float E1a = expf(-TRf / T1[b0]);
    float E1b = expf(-TRf / T1[b1c]);
    float E2a = expf(-TRf / T2[b0]);
    float E2b = expf(-TRf / T2[b1c]);
    float rAa = 1.0f - E1a;
    float rAb = 1.0f - E1b;
    float b1va = B1[b0];
    float b1vb = B1[b1c];

    const float TWO_PI_OVER_1000 = 6.283185307179586e-3f;
    float sphA, cphA, sphB, cphB;
    sincosf(TWO_PI_OVER_1000 * B0[b0]  * TRf, &sphA, &cphA);
    sincosf(TWO_PI_OVER_1000 * B0[b1c] * TRf, &sphB, &cphB);

    // Fused relaxation + off-resonance constants
    float cEa = E2a * cphA, sEa = E2a * sphA;
    float cEb = E2b * cphB, sEb = E2b * sphB;

    // State registers, two independent systems
    float FpRa = 0.f, FpIa = 0.f, FmRa = 0.f, FmIa = 0.f;
    float FpRb = 0.f, FpIb = 0.f, FmRb = 0.f, FmIb = 0.f;
    float Za = (lane == 0) ? 1.0f : 0.0f;
    float Zb = Za;

    size_t planeStride = (size_t)B * N_STATES;
    size_t pulseStride = 5 * planeStride;
    float* outp = out + (size_t)b0 * N_STATES + lane;   // element b1 = outp + N_STATES
    bool st0 = (lane < N_STATES);
    bool st1 = st0 && has1;
    bool isLane0 = (lane == 0);
    bool isLast  = (lane == N_STATES - 1);

    #pragma unroll 2
    for (int p = 0; p < N_PULSES; p++) {
        // ---- fused E2 relaxation + B0 rotation ----
        float r;
        r    = FpRa * cEa - FpIa * sEa;  FpIa = FpRa * sEa + FpIa * cEa;  FpRa = r;
        r    = FmRa * cEa + FmIa * sEa;  FmIa = FmIa * cEa - FmRa * sEa;  FmRa = r;
        r    = FpRb * cEb - FpIb * sEb;  FpIb = FpRb * sEb + FpIb * cEb;  FpRb = r;
        r    = FmRb * cEb + FmIb * sEb;  FmIb = FmIb * cEb - FmRb * sEb;  FmRb = r;

        Za *= E1a;  Zb *= E1b;
        if (isLane0) { Za += rAa; Zb += rAb; }

        // ---- RF mixing ----
        float ha = s_ha[p];
        float4 c = s_c[p];
        float cb = c.x, sb = c.y, c2b = c.z, s2b = c.w;

        float saA, caA, saB, caB;
        __sincosf(ha * b1va, &saA, &caA);
        __sincosf(ha * b1vb, &saB, &caB);

        float ca2a = caA * caA, sa2a = saA * saA, csa = caA * saA;
        float ca2b = caB * caB, sa2b = saB * saB, csb_ = caB * saB;
        float cZa = csa * Za;
        float cZb = csb_ * Zb;

        float FpnRa = ca2a * FpRa + sa2a * ( FmRa * c2b + FmIa * s2b) - cZa * sb;
        float FpnIa = ca2a * FpIa + sa2a * ( FmRa * s2b - FmIa * c2b) + cZa * cb;
        float FmnRa = ca2a * FmRa + sa2a * ( FpRa * c2b - FpIa * s2b) - cZa * sb;
        float FmnIa = ca2a * FmIa + sa2a * (-FpRa * s2b - FpIa * c2b) - cZa * cb;
        float DimA  = (FpIa * cb - FpRa * sb) - (FmRa * sb + FmIa * cb);
        float ZnA   = csa * DimA + (ca2a - sa2a) * Za;

        float FpnRb = ca2b * FpRb + sa2b * ( FmRb * c2b + FmIb * s2b) - cZb * sb;
        float FpnIb = ca2b * FpIb + sa2b * ( FmRb * s2b - FmIb * c2b) + cZb * cb;
        float FmnRb = ca2b * FmRb + sa2b * ( FpRb * c2b - FpIb * s2b) - cZb * sb;
        float FmnIb = ca2b * FmIb + sa2b * (-FpRb * s2b - FpIb * c2b) - cZb * cb;
        float DimB  = (FpIb * cb - FpRb * sb) - (FmRb * sb + FmIb * cb);
        float ZnB   = csb_ * DimB + (ca2b - sa2b) * Zb;

        // ---- gradient shift via shuffles (8 independent) ----
        float uRa = __shfl_up_sync  (0xffffffffu, FpnRa, 1);
        float uIa = __shfl_up_sync  (0xffffffffu, FpnIa, 1);
        float dRa = __shfl_down_sync(0xffffffffu, FmnRa, 1);
        float dIa = __shfl_down_sync(0xffffffffu, FmnIa, 1);
        float uRb = __shfl_up_sync  (0xffffffffu, FpnRb, 1);
        float uIb = __shfl_up_sync  (0xffffffffu, FpnIb, 1);
        float dRb = __shfl_down_sync(0xffffffffu, FmnRb, 1);
        float dIb = __shfl_down_sync(0xffffffffu, FmnIb, 1);
        if (isLane0) { uRa = 0.f; uIa = 0.f; uRb = 0.f; uIb = 0.f; }
        if (isLast)  { dRa = 0.f; dIa = 0.f; dRb = 0.f; dIb = 0.f; }
        FpRa = uRa; FpIa = uIa; FmRa = dRa; FmIa = dIa; Za = ZnA;
        FpRb = uRb; FpIb = uIb; FmRb = dRb; FmIb = dIb; Zb = ZnB;

        // ---- stores: outs[p, comp, b, state] ----
        if (st0) {
            outp[0]               = FpRa;
            outp[planeStride]     = FpIa;
            outp[2 * planeStride] = FmRa;
            outp[3 * planeStride] = FmIa;
            outp[4 * planeStride] = ZnA;
        }
        if (st1) {
            float* o1 = outp + N_STATES;
            o1[0]               = FpRb;
            o1[planeStride]     = FpIb;
            o1[2 * planeStride] = FmRb;
            o1[3 * planeStride] = FmIb;
            o1[4 * planeStride] = ZnB;
        }
        outp += pulseStride;
    }
}

extern "C" void kernel_launch(void* const* d_in, const int* in_sizes, int n_in,
                              void* d_out, int out_size)
{
    const float* flip   = (const float*)d_in[0];
    const float* phases = (const float*)d_in[1];
    const float* T1     = (const float*)d_in[2];
    const float* T2     = (const float*)d_in[3];
    const float* B0     = (const float*)d_in[4];
    const float* B1     = (const float*)d_in[5];
    const void*  trp    = d_in[6];
    float* out = (float*)d_out;

    int B = in_sizes[2];               // batch from T1
    int threads = 256;
    int warpsPerBlock = threads / 32;  // 8
    int elemsPerBlock = warpsPerBlock * 2;
    int blocks = (B + elemsPerBlock - 1) / elemsPerBlock;

    epg_kernel<<<blocks, threads>>>(flip, phases, T1, T2, B0, B1, trp, out, B);
}